// round 2
// baseline (speedup 1.0000x reference)
#include <cuda_runtime.h>
#include <cstdint>

#define BOX 256
#define KS 9
#define HALF 4
#define NN 32
#define NL 3
#define LATENT 8

// ---------------------------------------------------------------------------
// Fused decoder: per-thread = one (batch, point).
//   amp head:    [pos(3), z[b,7]] -> 32 -> 3x residual(32x32) -> sigmoid scalar
//   deform head: [pos(3), z[b,0:7]] -> 32 -> 3x residual(32x32) -> tanh(3) -> 3x3
//   project with r[b], splat 9x9 Gaussian kernel via atomicAdd (RED) into image
// ---------------------------------------------------------------------------
__global__ __launch_bounds__(256)
void decoder_kernel(
    const float* __restrict__ z, const float* __restrict__ r,
    const float* __restrict__ pos, const float* __restrict__ amp,
    const float* __restrict__ linamp1_W, const float* __restrict__ ampblock_W,
    const float* __restrict__ ampblock_b, const float* __restrict__ linamp2_W,
    const float* __restrict__ linamp2_b, const float* __restrict__ lin0_W,
    const float* __restrict__ deform_W, const float* __restrict__ deform_b,
    const float* __restrict__ lin1a_W, const float* __restrict__ lin1b_W,
    const float* __restrict__ k2, const int* __restrict__ dflag_p,
    float* __restrict__ out_img, float* __restrict__ out_posdef,
    float* __restrict__ out_res, float* __restrict__ out_ampcorr,
    int P)
{
    __shared__ float sA1[NN * 4];          // linamp1_W
    __shared__ float sAW[NL * NN * NN];    // ampblock_W
    __shared__ float sAB[NL * NN];         // ampblock_b
    __shared__ float sA2W[NN];             // linamp2_W
    __shared__ float sL0[NN * 10];         // lin0_W
    __shared__ float sDW[NL * NN * NN];    // deform_W
    __shared__ float sDB[NL * NN];         // deform_b
    __shared__ float sL1a[3 * NN];         // lin1a_W
    __shared__ float sL1b[9];              // lin1b_W
    __shared__ float sK2[KS * KS];         // splat kernel
    __shared__ float sZ[LATENT];           // z[b]
    __shared__ float sR[9];                // r[b]
    __shared__ float sScal[2];             // amp, linamp2_b
    __shared__ int   sD;

    const int b   = blockIdx.y;
    const int tid = threadIdx.x;
    const int nt  = blockDim.x;

    for (int i = tid; i < NN * 4;       i += nt) sA1[i]  = linamp1_W[i];
    for (int i = tid; i < NL * NN * NN; i += nt) { sAW[i] = ampblock_W[i]; sDW[i] = deform_W[i]; }
    for (int i = tid; i < NL * NN;      i += nt) { sAB[i] = ampblock_b[i]; sDB[i] = deform_b[i]; }
    for (int i = tid; i < NN;           i += nt) sA2W[i] = linamp2_W[i];
    for (int i = tid; i < NN * 10;      i += nt) sL0[i]  = lin0_W[i];
    for (int i = tid; i < 3 * NN;       i += nt) sL1a[i] = lin1a_W[i];
    for (int i = tid; i < 9;            i += nt) { sL1b[i] = lin1b_W[i]; sR[i] = r[b * 9 + i]; }
    for (int i = tid; i < KS * KS;      i += nt) sK2[i]  = k2[i];
    for (int i = tid; i < LATENT;       i += nt) sZ[i]   = z[b * LATENT + i];
    if (tid == 0) { sScal[0] = amp[0]; sScal[1] = linamp2_b[0]; sD = dflag_p[0]; }
    __syncthreads();

    const int p = blockIdx.x * nt + tid;
    if (p >= P) return;

    const float px = pos[3 * p + 0];
    const float py = pos[3 * p + 1];
    const float pz = pos[3 * p + 2];

    float a[NN], t[NN];

    // ---------------- amplitude head ----------------
    {
        const float zl = sZ[LATENT - 1];
#pragma unroll
        for (int i = 0; i < NN; i++) {
            const float4 w = *(const float4*)&sA1[i * 4];
            a[i] = w.x * px + w.y * py + w.z * pz + w.w * zl;
        }
#pragma unroll
        for (int l = 0; l < NL; l++) {
            const float* W  = &sAW[l * NN * NN];
            const float* Bb = &sAB[l * NN];
#pragma unroll
            for (int i = 0; i < NN; i++) {
                float acc = Bb[i];
#pragma unroll
                for (int j = 0; j < NN; j += 4) {
                    const float4 w = *(const float4*)&W[i * NN + j];
                    acc += w.x * a[j] + w.y * a[j + 1] + w.z * a[j + 2] + w.w * a[j + 3];
                }
                t[i] = fmaxf(acc, 0.0f) + a[i];
            }
#pragma unroll
            for (int i = 0; i < NN; i++) a[i] = t[i];
        }
    }
    float s2 = sScal[1];
#pragma unroll
    for (int i = 0; i < NN; i++) s2 += sA2W[i] * a[i];
    const float amp_corr = 1.0f / (1.0f + __expf(-s2));

    // ---------------- deformation head ----------------
    float rx = 0.0f, ry = 0.0f, rz = 0.0f;
    if (sD > 0) {
#pragma unroll
        for (int i = 0; i < NN; i++) {
            const float* w = &sL0[i * 10];
            float acc = w[0] * px + w[1] * py + w[2] * pz;
#pragma unroll
            for (int j = 0; j < 7; j++) acc += w[3 + j] * sZ[j];
            a[i] = acc;
        }
#pragma unroll
        for (int l = 0; l < NL; l++) {
            const float* W  = &sDW[l * NN * NN];
            const float* Bb = &sDB[l * NN];
#pragma unroll
            for (int i = 0; i < NN; i++) {
                float acc = Bb[i];
#pragma unroll
                for (int j = 0; j < NN; j += 4) {
                    const float4 w = *(const float4*)&W[i * NN + j];
                    acc += w.x * a[j] + w.y * a[j + 1] + w.z * a[j + 2] + w.w * a[j + 3];
                }
                t[i] = fmaxf(acc, 0.0f) + a[i];
            }
#pragma unroll
            for (int i = 0; i < NN; i++) a[i] = t[i];
        }
        float v0 = 0.0f, v1 = 0.0f, v2 = 0.0f;
#pragma unroll
        for (int i = 0; i < NN; i++) {
            v0 += sL1a[0 * NN + i] * a[i];
            v1 += sL1a[1 * NN + i] * a[i];
            v2 += sL1a[2 * NN + i] * a[i];
        }
        v0 = tanhf(v0); v1 = tanhf(v1); v2 = tanhf(v2);
        rx = sL1b[0] * v0 + sL1b[1] * v1 + sL1b[2] * v2;
        ry = sL1b[3] * v0 + sL1b[4] * v1 + sL1b[5] * v2;
        rz = sL1b[6] * v0 + sL1b[7] * v1 + sL1b[8] * v2;
    }

    const float pdx = px + rx, pdy = py + ry, pdz = pz + rz;

    // ---------------- outputs (aux) ----------------
    const long long bp = (long long)b * P + p;
    if (out_posdef) {
        out_posdef[bp * 3 + 0] = pdx;
        out_posdef[bp * 3 + 1] = pdy;
        out_posdef[bp * 3 + 2] = pdz;
        out_res[bp * 3 + 0] = rx;
        out_res[bp * 3 + 1] = ry;
        out_res[bp * 3 + 2] = rz;
        out_ampcorr[bp] = amp_corr;
    }

    // ---------------- project + splat ----------------
    const float projx = sR[0] * pdx + sR[1] * pdy + sR[2] * pdz;
    const float projy = sR[3] * pdx + sR[4] * pdy + sR[5] * pdz;

    const float amps = sScal[0] * amp_corr;
    const float pixx = (projx + 0.5f) * (float)(BOX - 1);
    const float pixy = (projy + 0.5f) * (float)(BOX - 1);
    const int cx = __float2int_rn(pixx);  // round-half-to-even, matches jnp.round
    const int cy = __float2int_rn(pixy);

    float* img_b = out_img + (size_t)b * BOX * BOX;
#pragma unroll
    for (int ky = 0; ky < KS; ky++) {
        const int yy = cy + ky - HALF;
        if ((unsigned)yy < (unsigned)BOX) {
            float* row = img_b + (size_t)yy * BOX;
#pragma unroll
            for (int kx = 0; kx < KS; kx++) {
                const int xx = cx + kx - HALF;
                if ((unsigned)xx < (unsigned)BOX)
                    atomicAdd(row + xx, amps * sK2[ky * KS + kx]);
            }
        }
    }
}

extern "C" void kernel_launch(void* const* d_in, const int* in_sizes, int n_in,
                              void* d_out, int out_size)
{
    const float* z          = (const float*)d_in[0];
    const float* r          = (const float*)d_in[1];
    const float* pos        = (const float*)d_in[2];
    const float* amp        = (const float*)d_in[3];
    const float* linamp1_W  = (const float*)d_in[4];
    const float* ampblock_W = (const float*)d_in[5];
    const float* ampblock_b = (const float*)d_in[6];
    const float* linamp2_W  = (const float*)d_in[7];
    const float* linamp2_b  = (const float*)d_in[8];
    const float* lin0_W     = (const float*)d_in[9];
    const float* deform_W   = (const float*)d_in[10];
    const float* deform_b   = (const float*)d_in[11];
    const float* lin1a_W    = (const float*)d_in[12];
    const float* lin1b_W    = (const float*)d_in[13];
    const float* k2         = (const float*)d_in[14];
    const int*   dflag      = (const int*)d_in[15];

    const int B = in_sizes[0] / LATENT;       // 16
    const int P = in_sizes[2] / 3;            // 20000

    float* out = (float*)d_out;
    const long long img_elems = (long long)B * BOX * BOX;          // 1,048,576
    const long long aux_elems = (long long)B * P * 7;              // pos_def+res+amp_corr
    // zero the splat target (graph-capturable, no allocation)
    cudaMemsetAsync(out, 0, (size_t)img_elems * sizeof(float));

    float *out_pd = nullptr, *out_res = nullptr, *out_ac = nullptr;
    if ((long long)out_size >= img_elems + aux_elems) {
        out_pd  = out + img_elems;
        out_res = out_pd + (long long)B * P * 3;
        out_ac  = out_res + (long long)B * P * 3;
    }

    dim3 grid((P + 255) / 256, B);
    decoder_kernel<<<grid, 256>>>(z, r, pos, amp, linamp1_W, ampblock_W,
                                  ampblock_b, linamp2_W, linamp2_b, lin0_W,
                                  deform_W, deform_b, lin1a_W, lin1b_W, k2,
                                  dflag, out, out_pd, out_res, out_ac, P);
}

// round 3
// speedup vs baseline: 1.0381x; 1.0381x over previous
#include <cuda_runtime.h>
#include <cstdint>

#define BOX 256
#define KS 9
#define HALF 4
#define NN 32
#define NL 3
#define LATENT 8

typedef unsigned long long ull;

// ---- packed fp32x2 helpers (SASS FFMA2 path, PTX-only) ----
__device__ __forceinline__ ull pk2(float lo, float hi) {
    ull r; asm("mov.b64 %0,{%1,%2};" : "=l"(r) : "f"(lo), "f"(hi)); return r;
}
__device__ __forceinline__ void upk2(ull v, float& lo, float& hi) {
    asm("mov.b64 {%0,%1},%2;" : "=f"(lo), "=f"(hi) : "l"(v));
}
__device__ __forceinline__ ull ffma2(ull a, ull b, ull c) {
    ull d; asm("fma.rn.f32x2 %0,%1,%2,%3;" : "=l"(d) : "l"(a), "l"(b), "l"(c)); return d;
}
__device__ __forceinline__ ull fadd2(ull a, ull b) {
    ull d; asm("add.rn.f32x2 %0,%1,%2;" : "=l"(d) : "l"(a), "l"(b)); return d;
}

// One residual layer on packed activations a2[16] (= 32 neurons).
// Wt is TRANSPOSED: Wt[j*32 + i] = W[i*32 + j]. Accumulation order: bias, then
// j = 0..31 ascending — identical order (and thus identical bits) to the
// reference-matching scalar version.
__device__ __forceinline__ void res_layer(ull a2[16], const float* __restrict__ Wt,
                                          const float* __restrict__ Bb)
{
    ull acc[16];
    const ull* bb = (const ull*)Bb;
#pragma unroll
    for (int k = 0; k < 16; k++) acc[k] = bb[k];
#pragma unroll
    for (int j = 0; j < 32; j++) {
        float alo, ahi; upk2(a2[j >> 1], alo, ahi);
        const float aj = (j & 1) ? ahi : alo;
        const ull ajd = pk2(aj, aj);
        const ulonglong2* row = (const ulonglong2*)(Wt + (j << 5));
#pragma unroll
        for (int m = 0; m < 8; m++) {
            const ulonglong2 w = row[m];
            acc[2 * m]     = ffma2(w.x, ajd, acc[2 * m]);
            acc[2 * m + 1] = ffma2(w.y, ajd, acc[2 * m + 1]);
        }
    }
#pragma unroll
    for (int k = 0; k < 16; k++) {
        float lo, hi; upk2(acc[k], lo, hi);
        lo = fmaxf(lo, 0.0f); hi = fmaxf(hi, 0.0f);
        a2[k] = fadd2(pk2(lo, hi), a2[k]);
    }
}

__global__ __launch_bounds__(256)
void decoder_kernel(
    const float* __restrict__ z, const float* __restrict__ r,
    const float* __restrict__ pos, const float* __restrict__ amp,
    const float* __restrict__ linamp1_W, const float* __restrict__ ampblock_W,
    const float* __restrict__ ampblock_b, const float* __restrict__ linamp2_W,
    const float* __restrict__ linamp2_b, const float* __restrict__ lin0_W,
    const float* __restrict__ deform_W, const float* __restrict__ deform_b,
    const float* __restrict__ lin1a_W, const float* __restrict__ lin1b_W,
    const float* __restrict__ k2, const int* __restrict__ dflag_p,
    float* __restrict__ out_img, float* __restrict__ out_posdef,
    float* __restrict__ out_res, float* __restrict__ out_ampcorr,
    int P)
{
    __shared__ alignas(16) float sA1[NN * 4];          // linamp1_W
    __shared__ alignas(16) float sAWt[NL * NN * NN];   // ampblock_W transposed
    __shared__ alignas(16) float sAB[NL * NN];         // ampblock_b
    __shared__ alignas(16) float sA2W[NN];             // linamp2_W
    __shared__ alignas(16) float sL0[NN * 10];         // lin0_W
    __shared__ alignas(16) float sDWt[NL * NN * NN];   // deform_W transposed
    __shared__ alignas(16) float sDB[NL * NN];         // deform_b
    __shared__ alignas(16) float sL1a[3 * NN];         // lin1a_W
    __shared__ float sL1b[9];
    __shared__ float sK2[KS * KS];
    __shared__ float sZ[LATENT];
    __shared__ float sR[9];
    __shared__ float sScal[2];
    __shared__ int   sD;

    const int b   = blockIdx.y;
    const int tid = threadIdx.x;
    const int nt  = blockDim.x;

    for (int i = tid; i < NN * 4; i += nt) sA1[i] = linamp1_W[i];
    // transposed fill: write-linear (conflict-free STS), strided gmem reads (L2-hot)
    for (int w = tid; w < NL * NN * NN; w += nt) {
        const int l = w >> 10, rem = w & 1023, j = rem >> 5, i = rem & 31;
        const int src = (l << 10) + (i << 5) + j;
        sAWt[w] = ampblock_W[src];
        sDWt[w] = deform_W[src];
    }
    for (int i = tid; i < NL * NN; i += nt) { sAB[i] = ampblock_b[i]; sDB[i] = deform_b[i]; }
    for (int i = tid; i < NN;      i += nt) sA2W[i] = linamp2_W[i];
    for (int i = tid; i < NN * 10; i += nt) sL0[i]  = lin0_W[i];
    for (int i = tid; i < 3 * NN;  i += nt) sL1a[i] = lin1a_W[i];
    for (int i = tid; i < 9;       i += nt) { sL1b[i] = lin1b_W[i]; sR[i] = r[b * 9 + i]; }
    for (int i = tid; i < KS * KS; i += nt) sK2[i]  = k2[i];
    for (int i = tid; i < LATENT;  i += nt) sZ[i]   = z[b * LATENT + i];
    if (tid == 0) { sScal[0] = amp[0]; sScal[1] = linamp2_b[0]; sD = dflag_p[0]; }
    __syncthreads();

    const int p = blockIdx.x * nt + tid;
    if (p >= P) return;

    const float px = pos[3 * p + 0];
    const float py = pos[3 * p + 1];
    const float pz = pos[3 * p + 2];

    ull a2[16];

    // ---------------- amplitude head ----------------
    {
        const float zl = sZ[LATENT - 1];
#pragma unroll
        for (int k = 0; k < 16; k++) {
            const float4 w0 = *(const float4*)&sA1[(2 * k) * 4];
            const float4 w1 = *(const float4*)&sA1[(2 * k + 1) * 4];
            const float lo = w0.x * px + w0.y * py + w0.z * pz + w0.w * zl;
            const float hi = w1.x * px + w1.y * py + w1.z * pz + w1.w * zl;
            a2[k] = pk2(lo, hi);
        }
#pragma unroll
        for (int l = 0; l < NL; l++)
            res_layer(a2, &sAWt[l * NN * NN], &sAB[l * NN]);
    }
    float amp_corr;
    {
        // scalar sequential dot (preserves exact accumulation order)
        float s2 = sScal[1];
#pragma unroll
        for (int k = 0; k < 16; k++) {
            float lo, hi; upk2(a2[k], lo, hi);
            s2 += sA2W[2 * k] * lo;
            s2 += sA2W[2 * k + 1] * hi;
        }
        amp_corr = 1.0f / (1.0f + __expf(-s2));
    }

    // ---------------- deformation head ----------------
    float rx = 0.0f, ry = 0.0f, rz = 0.0f;
    if (sD > 0) {
#pragma unroll
        for (int k = 0; k < 16; k++) {
            float v[2];
#pragma unroll
            for (int h = 0; h < 2; h++) {
                const float* w = &sL0[(2 * k + h) * 10];
                float acc = w[0] * px + w[1] * py + w[2] * pz;
#pragma unroll
                for (int j = 0; j < 7; j++) acc += w[3 + j] * sZ[j];
                v[h] = acc;
            }
            a2[k] = pk2(v[0], v[1]);
        }
#pragma unroll
        for (int l = 0; l < NL; l++)
            res_layer(a2, &sDWt[l * NN * NN], &sDB[l * NN]);

        float av[NN];
#pragma unroll
        for (int k = 0; k < 16; k++) upk2(a2[k], av[2 * k], av[2 * k + 1]);

        float v0 = 0.0f, v1 = 0.0f, v2 = 0.0f;
#pragma unroll
        for (int i = 0; i < NN; i++) {
            v0 += sL1a[0 * NN + i] * av[i];
            v1 += sL1a[1 * NN + i] * av[i];
            v2 += sL1a[2 * NN + i] * av[i];
        }
        v0 = tanhf(v0); v1 = tanhf(v1); v2 = tanhf(v2);
        rx = sL1b[0] * v0 + sL1b[1] * v1 + sL1b[2] * v2;
        ry = sL1b[3] * v0 + sL1b[4] * v1 + sL1b[5] * v2;
        rz = sL1b[6] * v0 + sL1b[7] * v1 + sL1b[8] * v2;
    }

    const float pdx = px + rx, pdy = py + ry, pdz = pz + rz;

    // ---------------- outputs (aux) ----------------
    const long long bp = (long long)b * P + p;
    if (out_posdef) {
        out_posdef[bp * 3 + 0] = pdx;
        out_posdef[bp * 3 + 1] = pdy;
        out_posdef[bp * 3 + 2] = pdz;
        out_res[bp * 3 + 0] = rx;
        out_res[bp * 3 + 1] = ry;
        out_res[bp * 3 + 2] = rz;
        out_ampcorr[bp] = amp_corr;
    }

    // ---------------- project + splat ----------------
    const float projx = sR[0] * pdx + sR[1] * pdy + sR[2] * pdz;
    const float projy = sR[3] * pdx + sR[4] * pdy + sR[5] * pdz;

    const float amps = sScal[0] * amp_corr;
    const float pixx = (projx + 0.5f) * (float)(BOX - 1);
    const float pixy = (projy + 0.5f) * (float)(BOX - 1);
    const int cx = __float2int_rn(pixx);   // round-half-to-even, matches jnp.round
    const int cy = __float2int_rn(pixy);

    float* img_b = out_img + (size_t)b * BOX * BOX;
#pragma unroll
    for (int ky = 0; ky < KS; ky++) {
        const int yy = cy + ky - HALF;
        if ((unsigned)yy < (unsigned)BOX) {
            float* row = img_b + (size_t)yy * BOX;
#pragma unroll
            for (int kx = 0; kx < KS; kx++) {
                const int xx = cx + kx - HALF;
                if ((unsigned)xx < (unsigned)BOX)
                    atomicAdd(row + xx, amps * sK2[ky * KS + kx]);
            }
        }
    }
}

extern "C" void kernel_launch(void* const* d_in, const int* in_sizes, int n_in,
                              void* d_out, int out_size)
{
    const float* z          = (const float*)d_in[0];
    const float* r          = (const float*)d_in[1];
    const float* pos        = (const float*)d_in[2];
    const float* amp        = (const float*)d_in[3];
    const float* linamp1_W  = (const float*)d_in[4];
    const float* ampblock_W = (const float*)d_in[5];
    const float* ampblock_b = (const float*)d_in[6];
    const float* linamp2_W  = (const float*)d_in[7];
    const float* linamp2_b  = (const float*)d_in[8];
    const float* lin0_W     = (const float*)d_in[9];
    const float* deform_W   = (const float*)d_in[10];
    const float* deform_b   = (const float*)d_in[11];
    const float* lin1a_W    = (const float*)d_in[12];
    const float* lin1b_W    = (const float*)d_in[13];
    const float* k2         = (const float*)d_in[14];
    const int*   dflag      = (const int*)d_in[15];

    const int B = in_sizes[0] / LATENT;       // 16
    const int P = in_sizes[2] / 3;            // 20000

    float* out = (float*)d_out;
    const long long img_elems = (long long)B * BOX * BOX;
    const long long aux_elems = (long long)B * P * 7;
    cudaMemsetAsync(out, 0, (size_t)img_elems * sizeof(float));

    float *out_pd = nullptr, *out_res = nullptr, *out_ac = nullptr;
    if ((long long)out_size >= img_elems + aux_elems) {
        out_pd  = out + img_elems;
        out_res = out_pd + (long long)B * P * 3;
        out_ac  = out_res + (long long)B * P * 3;
    }

    dim3 grid((P + 255) / 256, B);
    decoder_kernel<<<grid, 256>>>(z, r, pos, amp, linamp1_W, ampblock_W,
                                  ampblock_b, linamp2_W, linamp2_b, lin0_W,
                                  deform_W, deform_b, lin1a_W, lin1b_W, k2,
                                  dflag, out, out_pd, out_res, out_ac, P);
}

// round 4
// speedup vs baseline: 1.1366x; 1.0949x over previous
#include <cuda_runtime.h>
#include <cstdint>

#define BOX 256
#define KS 9
#define HALF 4
#define NN 32
#define NL 3
#define LATENT 8

typedef unsigned long long ull;

// ---- packed fp32x2 helpers (SASS FFMA2 path, PTX-only) ----
__device__ __forceinline__ ull pk2(float lo, float hi) {
    ull r; asm("mov.b64 %0,{%1,%2};" : "=l"(r) : "f"(lo), "f"(hi)); return r;
}
__device__ __forceinline__ void upk2(ull v, float& lo, float& hi) {
    asm("mov.b64 {%0,%1},%2;" : "=f"(lo), "=f"(hi) : "l"(v));
}
__device__ __forceinline__ ull ffma2(ull a, ull b, ull c) {
    ull d; asm("fma.rn.f32x2 %0,%1,%2,%3;" : "=l"(d) : "l"(a), "l"(b), "l"(c)); return d;
}
__device__ __forceinline__ ull fadd2(ull a, ull b) {
    ull d; asm("add.rn.f32x2 %0,%1,%2;" : "=l"(d) : "l"(a), "l"(b)); return d;
}

// One residual layer on TWO points' packed activations (a0[16], a1[16]).
// Weight row LDS128s are shared between the two points -> 1 LDS : 4 FFMA2.
// Wt is TRANSPOSED: Wt[j*32+i] = W[i*32+j]. Per-point accumulation order is
// bias-then-j-ascending, identical to the passing R2 kernel.
__device__ __forceinline__ void res_layer2(ull a0[16], ull a1[16],
                                           const float* __restrict__ Wt,
                                           const float* __restrict__ Bb)
{
    ull acc0[16], acc1[16];
    const ull* bb = (const ull*)Bb;
#pragma unroll
    for (int k = 0; k < 16; k++) { acc0[k] = bb[k]; acc1[k] = bb[k]; }
#pragma unroll
    for (int j = 0; j < 32; j++) {
        float l0, h0, l1, h1;
        upk2(a0[j >> 1], l0, h0);
        upk2(a1[j >> 1], l1, h1);
        const float aj0 = (j & 1) ? h0 : l0;
        const float aj1 = (j & 1) ? h1 : l1;
        const ull d0 = pk2(aj0, aj0);
        const ull d1 = pk2(aj1, aj1);
        const ulonglong2* row = (const ulonglong2*)(Wt + (j << 5));
#pragma unroll
        for (int m = 0; m < 8; m++) {
            const ulonglong2 w = row[m];
            acc0[2 * m]     = ffma2(w.x, d0, acc0[2 * m]);
            acc1[2 * m]     = ffma2(w.x, d1, acc1[2 * m]);
            acc0[2 * m + 1] = ffma2(w.y, d0, acc0[2 * m + 1]);
            acc1[2 * m + 1] = ffma2(w.y, d1, acc1[2 * m + 1]);
        }
    }
#pragma unroll
    for (int k = 0; k < 16; k++) {
        float lo, hi;
        upk2(acc0[k], lo, hi);
        a0[k] = fadd2(pk2(fmaxf(lo, 0.0f), fmaxf(hi, 0.0f)), a0[k]);
        upk2(acc1[k], lo, hi);
        a1[k] = fadd2(pk2(fmaxf(lo, 0.0f), fmaxf(hi, 0.0f)), a1[k]);
    }
}

__global__ __launch_bounds__(128, 3)
void decoder_kernel(
    const float* __restrict__ z, const float* __restrict__ r,
    const float* __restrict__ pos, const float* __restrict__ amp,
    const float* __restrict__ linamp1_W, const float* __restrict__ ampblock_W,
    const float* __restrict__ ampblock_b, const float* __restrict__ linamp2_W,
    const float* __restrict__ linamp2_b, const float* __restrict__ lin0_W,
    const float* __restrict__ deform_W, const float* __restrict__ deform_b,
    const float* __restrict__ lin1a_W, const float* __restrict__ lin1b_W,
    const float* __restrict__ k2, const int* __restrict__ dflag_p,
    float* __restrict__ out_img, float* __restrict__ out_posdef,
    float* __restrict__ out_res, float* __restrict__ out_ampcorr,
    int P)
{
    __shared__ alignas(16) float sA1[NN * 4];          // linamp1_W
    __shared__ alignas(16) float sAWt[NL * NN * NN];   // ampblock_W transposed
    __shared__ alignas(16) float sAB[NL * NN];         // ampblock_b
    __shared__ alignas(16) float sA2W[NN];             // linamp2_W
    __shared__ alignas(16) float sL0[NN * 10];         // lin0_W
    __shared__ alignas(16) float sDWt[NL * NN * NN];   // deform_W transposed
    __shared__ alignas(16) float sDB[NL * NN];         // deform_b
    __shared__ alignas(16) float sL1a[3 * NN];         // lin1a_W
    __shared__ float sL1b[9];
    __shared__ float sK2[KS * KS];
    __shared__ float sZ[LATENT];
    __shared__ float sR[9];
    __shared__ float sScal[2];
    __shared__ int   sD;

    const int b   = blockIdx.y;
    const int tid = threadIdx.x;
    const int nt  = blockDim.x;   // 128

    for (int i = tid; i < NN * 4; i += nt) sA1[i] = linamp1_W[i];
    for (int w = tid; w < NL * NN * NN; w += nt) {
        const int l = w >> 10, rem = w & 1023, j = rem >> 5, i = rem & 31;
        const int src = (l << 10) + (i << 5) + j;
        sAWt[w] = ampblock_W[src];
        sDWt[w] = deform_W[src];
    }
    for (int i = tid; i < NL * NN; i += nt) { sAB[i] = ampblock_b[i]; sDB[i] = deform_b[i]; }
    for (int i = tid; i < NN;      i += nt) sA2W[i] = linamp2_W[i];
    for (int i = tid; i < NN * 10; i += nt) sL0[i]  = lin0_W[i];
    for (int i = tid; i < 3 * NN;  i += nt) sL1a[i] = lin1a_W[i];
    for (int i = tid; i < 9;       i += nt) { sL1b[i] = lin1b_W[i]; sR[i] = r[b * 9 + i]; }
    for (int i = tid; i < KS * KS; i += nt) sK2[i]  = k2[i];
    for (int i = tid; i < LATENT;  i += nt) sZ[i]   = z[b * LATENT + i];
    if (tid == 0) { sScal[0] = amp[0]; sScal[1] = linamp2_b[0]; sD = dflag_p[0]; }
    __syncthreads();

    const int p0 = blockIdx.x * (2 * nt) + tid;
    if (p0 >= P) return;
    const int  p1  = p0 + nt;
    const bool v1  = (p1 < P);
    const int  p1c = v1 ? p1 : p0;

    const float px0 = pos[3 * p0 + 0], py0 = pos[3 * p0 + 1], pz0 = pos[3 * p0 + 2];
    const float px1 = pos[3 * p1c + 0], py1 = pos[3 * p1c + 1], pz1 = pos[3 * p1c + 2];

    ull a0[16], a1[16];

    // ---------------- amplitude head ----------------
    {
        const float zl = sZ[LATENT - 1];
#pragma unroll
        for (int k = 0; k < 16; k++) {
            const float4 w0 = *(const float4*)&sA1[(2 * k) * 4];
            const float4 w1 = *(const float4*)&sA1[(2 * k + 1) * 4];
            a0[k] = pk2(w0.x * px0 + w0.y * py0 + w0.z * pz0 + w0.w * zl,
                        w1.x * px0 + w1.y * py0 + w1.z * pz0 + w1.w * zl);
            a1[k] = pk2(w0.x * px1 + w0.y * py1 + w0.z * pz1 + w0.w * zl,
                        w1.x * px1 + w1.y * py1 + w1.z * pz1 + w1.w * zl);
        }
#pragma unroll
        for (int l = 0; l < NL; l++)
            res_layer2(a0, a1, &sAWt[l * NN * NN], &sAB[l * NN]);
    }
    float amp_corr0, amp_corr1;
    {
        float s0 = sScal[1], s1 = sScal[1];
#pragma unroll
        for (int k = 0; k < 16; k++) {
            float lo, hi;
            upk2(a0[k], lo, hi);
            s0 += sA2W[2 * k] * lo;  s0 += sA2W[2 * k + 1] * hi;
            upk2(a1[k], lo, hi);
            s1 += sA2W[2 * k] * lo;  s1 += sA2W[2 * k + 1] * hi;
        }
        amp_corr0 = 1.0f / (1.0f + __expf(-s0));
        amp_corr1 = 1.0f / (1.0f + __expf(-s1));
    }

    // ---------------- deformation head ----------------
    float rx0 = 0.0f, ry0 = 0.0f, rz0 = 0.0f;
    float rx1 = 0.0f, ry1 = 0.0f, rz1 = 0.0f;
    if (sD > 0) {
#pragma unroll
        for (int k = 0; k < 16; k++) {
            float v0[2], v1v[2];
#pragma unroll
            for (int h = 0; h < 2; h++) {
                const float* w = &sL0[(2 * k + h) * 10];
                float acc0 = w[0] * px0 + w[1] * py0 + w[2] * pz0;
                float acc1 = w[0] * px1 + w[1] * py1 + w[2] * pz1;
#pragma unroll
                for (int j = 0; j < 7; j++) {
                    acc0 += w[3 + j] * sZ[j];
                    acc1 += w[3 + j] * sZ[j];
                }
                v0[h] = acc0; v1v[h] = acc1;
            }
            a0[k] = pk2(v0[0], v0[1]);
            a1[k] = pk2(v1v[0], v1v[1]);
        }
#pragma unroll
        for (int l = 0; l < NL; l++)
            res_layer2(a0, a1, &sDWt[l * NN * NN], &sDB[l * NN]);

        float u00 = 0.0f, u01 = 0.0f, u02 = 0.0f;
        float u10 = 0.0f, u11 = 0.0f, u12 = 0.0f;
#pragma unroll
        for (int k = 0; k < 16; k++) {
            float lo, hi;
            upk2(a0[k], lo, hi);
            u00 += sL1a[0 * NN + 2 * k] * lo;  u00 += sL1a[0 * NN + 2 * k + 1] * hi;
            u01 += sL1a[1 * NN + 2 * k] * lo;  u01 += sL1a[1 * NN + 2 * k + 1] * hi;
            u02 += sL1a[2 * NN + 2 * k] * lo;  u02 += sL1a[2 * NN + 2 * k + 1] * hi;
            upk2(a1[k], lo, hi);
            u10 += sL1a[0 * NN + 2 * k] * lo;  u10 += sL1a[0 * NN + 2 * k + 1] * hi;
            u11 += sL1a[1 * NN + 2 * k] * lo;  u11 += sL1a[1 * NN + 2 * k + 1] * hi;
            u12 += sL1a[2 * NN + 2 * k] * lo;  u12 += sL1a[2 * NN + 2 * k + 1] * hi;
        }
        u00 = tanhf(u00); u01 = tanhf(u01); u02 = tanhf(u02);
        u10 = tanhf(u10); u11 = tanhf(u11); u12 = tanhf(u12);
        rx0 = sL1b[0] * u00 + sL1b[1] * u01 + sL1b[2] * u02;
        ry0 = sL1b[3] * u00 + sL1b[4] * u01 + sL1b[5] * u02;
        rz0 = sL1b[6] * u00 + sL1b[7] * u01 + sL1b[8] * u02;
        rx1 = sL1b[0] * u10 + sL1b[1] * u11 + sL1b[2] * u12;
        ry1 = sL1b[3] * u10 + sL1b[4] * u11 + sL1b[5] * u12;
        rz1 = sL1b[6] * u10 + sL1b[7] * u11 + sL1b[8] * u12;
    }

    const float pdx0 = px0 + rx0, pdy0 = py0 + ry0, pdz0 = pz0 + rz0;
    const float pdx1 = px1 + rx1, pdy1 = py1 + ry1, pdz1 = pz1 + rz1;

    // ---------------- outputs (aux) ----------------
    if (out_posdef) {
        const long long bp0 = (long long)b * P + p0;
        out_posdef[bp0 * 3 + 0] = pdx0;
        out_posdef[bp0 * 3 + 1] = pdy0;
        out_posdef[bp0 * 3 + 2] = pdz0;
        out_res[bp0 * 3 + 0] = rx0;
        out_res[bp0 * 3 + 1] = ry0;
        out_res[bp0 * 3 + 2] = rz0;
        out_ampcorr[bp0] = amp_corr0;
        if (v1) {
            const long long bp1 = (long long)b * P + p1;
            out_posdef[bp1 * 3 + 0] = pdx1;
            out_posdef[bp1 * 3 + 1] = pdy1;
            out_posdef[bp1 * 3 + 2] = pdz1;
            out_res[bp1 * 3 + 0] = rx1;
            out_res[bp1 * 3 + 1] = ry1;
            out_res[bp1 * 3 + 2] = rz1;
            out_ampcorr[bp1] = amp_corr1;
        }
    }

    // ---------------- project + splat ----------------
    float* img_b = out_img + (size_t)b * BOX * BOX;
    const float ampg = sScal[0];

#pragma unroll
    for (int pt = 0; pt < 2; pt++) {
        if (pt == 1 && !v1) break;
        const float pdx = pt ? pdx1 : pdx0;
        const float pdy = pt ? pdy1 : pdy0;
        const float pdz = pt ? pdz1 : pdz0;
        const float ac  = pt ? amp_corr1 : amp_corr0;

        const float projx = sR[0] * pdx + sR[1] * pdy + sR[2] * pdz;
        const float projy = sR[3] * pdx + sR[4] * pdy + sR[5] * pdz;
        const float amps  = ampg * ac;
        const int cx = __float2int_rn((projx + 0.5f) * (float)(BOX - 1));
        const int cy = __float2int_rn((projy + 0.5f) * (float)(BOX - 1));

#pragma unroll
        for (int ky = 0; ky < KS; ky++) {
            const int yy = cy + ky - HALF;
            if ((unsigned)yy < (unsigned)BOX) {
                float* row = img_b + (size_t)yy * BOX;
#pragma unroll
                for (int kx = 0; kx < KS; kx++) {
                    const int xx = cx + kx - HALF;
                    if ((unsigned)xx < (unsigned)BOX)
                        atomicAdd(row + xx, amps * sK2[ky * KS + kx]);
                }
            }
        }
    }
}

extern "C" void kernel_launch(void* const* d_in, const int* in_sizes, int n_in,
                              void* d_out, int out_size)
{
    const float* z          = (const float*)d_in[0];
    const float* r          = (const float*)d_in[1];
    const float* pos        = (const float*)d_in[2];
    const float* amp        = (const float*)d_in[3];
    const float* linamp1_W  = (const float*)d_in[4];
    const float* ampblock_W = (const float*)d_in[5];
    const float* ampblock_b = (const float*)d_in[6];
    const float* linamp2_W  = (const float*)d_in[7];
    const float* linamp2_b  = (const float*)d_in[8];
    const float* lin0_W     = (const float*)d_in[9];
    const float* deform_W   = (const float*)d_in[10];
    const float* deform_b   = (const float*)d_in[11];
    const float* lin1a_W    = (const float*)d_in[12];
    const float* lin1b_W    = (const float*)d_in[13];
    const float* k2         = (const float*)d_in[14];
    const int*   dflag      = (const int*)d_in[15];

    const int B = in_sizes[0] / LATENT;       // 16
    const int P = in_sizes[2] / 3;            // 20000

    float* out = (float*)d_out;
    const long long img_elems = (long long)B * BOX * BOX;
    const long long aux_elems = (long long)B * P * 7;
    cudaMemsetAsync(out, 0, (size_t)img_elems * sizeof(float));

    float *out_pd = nullptr, *out_res = nullptr, *out_ac = nullptr;
    if ((long long)out_size >= img_elems + aux_elems) {
        out_pd  = out + img_elems;
        out_res = out_pd + (long long)B * P * 3;
        out_ac  = out_res + (long long)B * P * 3;
    }

    dim3 grid((P + 255) / 256, B);
    decoder_kernel<<<grid, 128>>>(z, r, pos, amp, linamp1_W, ampblock_W,
                                  ampblock_b, linamp2_W, linamp2_b, lin0_W,
                                  deform_W, deform_b, lin1a_W, lin1b_W, k2,
                                  dflag, out, out_pd, out_res, out_ac, P);
}

// round 6
// speedup vs baseline: 1.7054x; 1.5005x over previous
#include <cuda_runtime.h>
#include <cstdint>

#define BOX 256
#define KS 9
#define HALF 4
#define NN 32
#define NL 3
#define LATENT 8

typedef unsigned long long ull;

// ---- packed fp32x2 helpers (SASS FFMA2 path, PTX-only) ----
__device__ __forceinline__ ull pk2(float lo, float hi) {
    ull r; asm("mov.b64 %0,{%1,%2};" : "=l"(r) : "f"(lo), "f"(hi)); return r;
}
__device__ __forceinline__ void upk2(ull v, float& lo, float& hi) {
    asm("mov.b64 {%0,%1},%2;" : "=f"(lo), "=f"(hi) : "l"(v));
}
__device__ __forceinline__ ull ffma2(ull a, ull b, ull c) {
    ull d; asm("fma.rn.f32x2 %0,%1,%2,%3;" : "=l"(d) : "l"(a), "l"(b), "l"(c)); return d;
}
__device__ __forceinline__ ull fadd2(ull a, ull b) {
    ull d; asm("add.rn.f32x2 %0,%1,%2;" : "=l"(d) : "l"(a), "l"(b)); return d;
}
__device__ __forceinline__ ull fmul2(ull a, ull b) {
    ull d; asm("mul.rn.f32x2 %0,%1,%2;" : "=l"(d) : "l"(a), "l"(b)); return d;
}
__device__ __forceinline__ void red4(float* p, float a, float b, float c, float d) {
    asm volatile("red.global.add.v4.f32 [%0], {%1,%2,%3,%4};"
                 :: "l"(p), "f"(a), "f"(b), "f"(c), "f"(d) : "memory");
}

// One residual layer on TWO points' packed activations (a0[16], a1[16]).
// Weight row LDS128s are shared between the two points -> 1 LDS : 4 FFMA2.
// Wt is TRANSPOSED: Wt[j*32+i] = W[i*32+j]. Per-point accumulation order is
// bias-then-j-ascending, identical to the passing R3 kernel.
__device__ __forceinline__ void res_layer2(ull a0[16], ull a1[16],
                                           const float* __restrict__ Wt,
                                           const float* __restrict__ Bb)
{
    ull acc0[16], acc1[16];
    const ull* bb = (const ull*)Bb;
#pragma unroll
    for (int k = 0; k < 16; k++) { acc0[k] = bb[k]; acc1[k] = bb[k]; }
#pragma unroll
    for (int j = 0; j < 32; j++) {
        float l0, h0, l1, h1;
        upk2(a0[j >> 1], l0, h0);
        upk2(a1[j >> 1], l1, h1);
        const float aj0 = (j & 1) ? h0 : l0;
        const float aj1 = (j & 1) ? h1 : l1;
        const ull d0 = pk2(aj0, aj0);
        const ull d1 = pk2(aj1, aj1);
        const ulonglong2* row = (const ulonglong2*)(Wt + (j << 5));
#pragma unroll
        for (int m = 0; m < 8; m++) {
            const ulonglong2 w = row[m];
            acc0[2 * m]     = ffma2(w.x, d0, acc0[2 * m]);
            acc1[2 * m]     = ffma2(w.x, d1, acc1[2 * m]);
            acc0[2 * m + 1] = ffma2(w.y, d0, acc0[2 * m + 1]);
            acc1[2 * m + 1] = ffma2(w.y, d1, acc1[2 * m + 1]);
        }
    }
#pragma unroll
    for (int k = 0; k < 16; k++) {
        float lo, hi;
        upk2(acc0[k], lo, hi);
        a0[k] = fadd2(pk2(fmaxf(lo, 0.0f), fmaxf(hi, 0.0f)), a0[k]);
        upk2(acc1[k], lo, hi);
        a1[k] = fadd2(pk2(fmaxf(lo, 0.0f), fmaxf(hi, 0.0f)), a1[k]);
    }
}

__global__ __launch_bounds__(128, 3)
void decoder_kernel(
    const float* __restrict__ z, const float* __restrict__ r,
    const float* __restrict__ pos, const float* __restrict__ amp,
    const float* __restrict__ linamp1_W, const float* __restrict__ ampblock_W,
    const float* __restrict__ ampblock_b, const float* __restrict__ linamp2_W,
    const float* __restrict__ linamp2_b, const float* __restrict__ lin0_W,
    const float* __restrict__ deform_W, const float* __restrict__ deform_b,
    const float* __restrict__ lin1a_W, const float* __restrict__ lin1b_W,
    const float* __restrict__ k2, const int* __restrict__ dflag_p,
    float* __restrict__ out_img, float* __restrict__ out_posdef,
    float* __restrict__ out_res, float* __restrict__ out_ampcorr,
    int P)
{
    __shared__ alignas(16) float sA1[NN * 4];          // linamp1_W
    __shared__ alignas(16) float sAWt[NL * NN * NN];   // ampblock_W transposed
    __shared__ alignas(16) float sAB[NL * NN];         // ampblock_b
    __shared__ alignas(16) float sA2W[NN];             // linamp2_W
    __shared__ alignas(16) float sL0[NN * 10];         // lin0_W
    __shared__ alignas(16) float sDWt[NL * NN * NN];   // deform_W transposed
    __shared__ alignas(16) float sDB[NL * NN];         // deform_b
    __shared__ alignas(16) float sL1a[3 * NN];         // lin1a_W
    __shared__ alignas(16) float sK2pad[4 * KS * 12];  // 4 x-shifts, 12-wide zero-padded rows
    __shared__ float sL1b[9];
    __shared__ float sK2[KS * KS];
    __shared__ float sZ[LATENT];
    __shared__ float sR[9];
    __shared__ float sScal[2];
    __shared__ int   sD;

    const int b   = blockIdx.y;
    const int tid = threadIdx.x;
    const int nt  = blockDim.x;   // 128

    for (int i = tid; i < NN * 4; i += nt) sA1[i] = linamp1_W[i];
    for (int w = tid; w < NL * NN * NN; w += nt) {
        const int l = w >> 10, rem = w & 1023, j = rem >> 5, i = rem & 31;
        const int src = (l << 10) + (i << 5) + j;
        sAWt[w] = ampblock_W[src];
        sDWt[w] = deform_W[src];
    }
    for (int i = tid; i < NL * NN; i += nt) { sAB[i] = ampblock_b[i]; sDB[i] = deform_b[i]; }
    for (int i = tid; i < NN;      i += nt) sA2W[i] = linamp2_W[i];
    for (int i = tid; i < NN * 10; i += nt) sL0[i]  = lin0_W[i];
    for (int i = tid; i < 3 * NN;  i += nt) sL1a[i] = lin1a_W[i];
    for (int i = tid; i < 9;       i += nt) { sL1b[i] = lin1b_W[i]; sR[i] = r[b * 9 + i]; }
    for (int i = tid; i < KS * KS; i += nt) sK2[i]  = k2[i];
    // shift-padded kernel copies: sK2pad[o][ky][c] = (o<=c<o+9) ? k2[ky][c-o] : 0
    for (int i = tid; i < 4 * KS * 12; i += nt) {
        const int o = i / (KS * 12), rem = i % (KS * 12);
        const int ky = rem / 12, c = rem % 12;
        sK2pad[i] = (c >= o && c < o + KS) ? k2[ky * KS + (c - o)] : 0.0f;
    }
    for (int i = tid; i < LATENT;  i += nt) sZ[i]   = z[b * LATENT + i];
    if (tid == 0) { sScal[0] = amp[0]; sScal[1] = linamp2_b[0]; sD = dflag_p[0]; }
    __syncthreads();

    const int p0 = blockIdx.x * (2 * nt) + tid;
    if (p0 >= P) return;
    const int  p1  = p0 + nt;
    const bool v1  = (p1 < P);
    const int  p1c = v1 ? p1 : p0;

    const float px0 = pos[3 * p0 + 0], py0 = pos[3 * p0 + 1], pz0 = pos[3 * p0 + 2];
    const float px1 = pos[3 * p1c + 0], py1 = pos[3 * p1c + 1], pz1 = pos[3 * p1c + 2];

    ull a0[16], a1[16];

    // ---------------- amplitude head ----------------
    {
        const float zl = sZ[LATENT - 1];
#pragma unroll
        for (int k = 0; k < 16; k++) {
            const float4 w0 = *(const float4*)&sA1[(2 * k) * 4];
            const float4 w1 = *(const float4*)&sA1[(2 * k + 1) * 4];
            a0[k] = pk2(w0.x * px0 + w0.y * py0 + w0.z * pz0 + w0.w * zl,
                        w1.x * px0 + w1.y * py0 + w1.z * pz0 + w1.w * zl);
            a1[k] = pk2(w0.x * px1 + w0.y * py1 + w0.z * pz1 + w0.w * zl,
                        w1.x * px1 + w1.y * py1 + w1.z * pz1 + w1.w * zl);
        }
#pragma unroll
        for (int l = 0; l < NL; l++)
            res_layer2(a0, a1, &sAWt[l * NN * NN], &sAB[l * NN]);
    }
    float amp_corr0, amp_corr1;
    {
        float s0 = sScal[1], s1 = sScal[1];
#pragma unroll
        for (int k = 0; k < 16; k++) {
            float lo, hi;
            upk2(a0[k], lo, hi);
            s0 += sA2W[2 * k] * lo;  s0 += sA2W[2 * k + 1] * hi;
            upk2(a1[k], lo, hi);
            s1 += sA2W[2 * k] * lo;  s1 += sA2W[2 * k + 1] * hi;
        }
        amp_corr0 = 1.0f / (1.0f + __expf(-s0));
        amp_corr1 = 1.0f / (1.0f + __expf(-s1));
    }

    // ---------------- deformation head ----------------
    float rx0 = 0.0f, ry0 = 0.0f, rz0 = 0.0f;
    float rx1 = 0.0f, ry1 = 0.0f, rz1 = 0.0f;
    if (sD > 0) {
#pragma unroll
        for (int k = 0; k < 16; k++) {
            float v0[2], v1v[2];
#pragma unroll
            for (int h = 0; h < 2; h++) {
                const float* w = &sL0[(2 * k + h) * 10];
                float acc0 = w[0] * px0 + w[1] * py0 + w[2] * pz0;
                float acc1 = w[0] * px1 + w[1] * py1 + w[2] * pz1;
#pragma unroll
                for (int j = 0; j < 7; j++) {
                    acc0 += w[3 + j] * sZ[j];
                    acc1 += w[3 + j] * sZ[j];
                }
                v0[h] = acc0; v1v[h] = acc1;
            }
            a0[k] = pk2(v0[0], v0[1]);
            a1[k] = pk2(v1v[0], v1v[1]);
        }
#pragma unroll
        for (int l = 0; l < NL; l++)
            res_layer2(a0, a1, &sDWt[l * NN * NN], &sDB[l * NN]);

        float u00 = 0.0f, u01 = 0.0f, u02 = 0.0f;
        float u10 = 0.0f, u11 = 0.0f, u12 = 0.0f;
#pragma unroll
        for (int k = 0; k < 16; k++) {
            float lo, hi;
            upk2(a0[k], lo, hi);
            u00 += sL1a[0 * NN + 2 * k] * lo;  u00 += sL1a[0 * NN + 2 * k + 1] * hi;
            u01 += sL1a[1 * NN + 2 * k] * lo;  u01 += sL1a[1 * NN + 2 * k + 1] * hi;
            u02 += sL1a[2 * NN + 2 * k] * lo;  u02 += sL1a[2 * NN + 2 * k + 1] * hi;
            upk2(a1[k], lo, hi);
            u10 += sL1a[0 * NN + 2 * k] * lo;  u10 += sL1a[0 * NN + 2 * k + 1] * hi;
            u11 += sL1a[1 * NN + 2 * k] * lo;  u11 += sL1a[1 * NN + 2 * k + 1] * hi;
            u12 += sL1a[2 * NN + 2 * k] * lo;  u12 += sL1a[2 * NN + 2 * k + 1] * hi;
        }
        u00 = tanhf(u00); u01 = tanhf(u01); u02 = tanhf(u02);
        u10 = tanhf(u10); u11 = tanhf(u11); u12 = tanhf(u12);
        rx0 = sL1b[0] * u00 + sL1b[1] * u01 + sL1b[2] * u02;
        ry0 = sL1b[3] * u00 + sL1b[4] * u01 + sL1b[5] * u02;
        rz0 = sL1b[6] * u00 + sL1b[7] * u01 + sL1b[8] * u02;
        rx1 = sL1b[0] * u10 + sL1b[1] * u11 + sL1b[2] * u12;
        ry1 = sL1b[3] * u10 + sL1b[4] * u11 + sL1b[5] * u12;
        rz1 = sL1b[6] * u10 + sL1b[7] * u11 + sL1b[8] * u12;
    }

    const float pdx0 = px0 + rx0, pdy0 = py0 + ry0, pdz0 = pz0 + rz0;
    const float pdx1 = px1 + rx1, pdy1 = py1 + ry1, pdz1 = pz1 + rz1;

    // ---------------- outputs (aux) ----------------
    if (out_posdef) {
        const long long bp0 = (long long)b * P + p0;
        out_posdef[bp0 * 3 + 0] = pdx0;
        out_posdef[bp0 * 3 + 1] = pdy0;
        out_posdef[bp0 * 3 + 2] = pdz0;
        out_res[bp0 * 3 + 0] = rx0;
        out_res[bp0 * 3 + 1] = ry0;
        out_res[bp0 * 3 + 2] = rz0;
        out_ampcorr[bp0] = amp_corr0;
        if (v1) {
            const long long bp1 = (long long)b * P + p1;
            out_posdef[bp1 * 3 + 0] = pdx1;
            out_posdef[bp1 * 3 + 1] = pdy1;
            out_posdef[bp1 * 3 + 2] = pdz1;
            out_res[bp1 * 3 + 0] = rx1;
            out_res[bp1 * 3 + 1] = ry1;
            out_res[bp1 * 3 + 2] = rz1;
            out_ampcorr[bp1] = amp_corr1;
        }
    }

    // ---------------- project + splat ----------------
    float* img_b = out_img + (size_t)b * BOX * BOX;
    const float ampg = sScal[0];

#pragma unroll
    for (int pt = 0; pt < 2; pt++) {
        if (pt == 1 && !v1) break;
        const float pdx = pt ? pdx1 : pdx0;
        const float pdy = pt ? pdy1 : pdy0;
        const float pdz = pt ? pdz1 : pdz0;
        const float ac  = pt ? amp_corr1 : amp_corr0;

        const float projx = sR[0] * pdx + sR[1] * pdy + sR[2] * pdz;
        const float projy = sR[3] * pdx + sR[4] * pdy + sR[5] * pdz;
        const float amps  = ampg * ac;
        const int cx = __float2int_rn((projx + 0.5f) * (float)(BOX - 1));
        const int cy = __float2int_rn((projy + 0.5f) * (float)(BOX - 1));

        const int x0  = cx - HALF;
        const int qx0 = x0 & ~3;           // 16B-aligned window start
        const int o   = x0 - qx0;          // 0..3

        if (qx0 >= 0 && qx0 + 12 <= BOX) {
            // fast path: three red.global.add.v4.f32 per valid row
            const ull ampd = pk2(amps, amps);
            const ulonglong2* kp =
                (const ulonglong2*)&sK2pad[o * (KS * 12)];
#pragma unroll
            for (int ky = 0; ky < KS; ky++) {
                const int yy = cy + ky - HALF;
                if ((unsigned)yy < (unsigned)BOX) {
                    float* dst = img_b + (size_t)yy * BOX + qx0;
                    const ulonglong2 q0 = kp[ky * 3 + 0];
                    const ulonglong2 q1 = kp[ky * 3 + 1];
                    const ulonglong2 q2 = kp[ky * 3 + 2];
                    float f0, f1, f2, f3;
                    upk2(fmul2(q0.x, ampd), f0, f1);
                    upk2(fmul2(q0.y, ampd), f2, f3);
                    red4(dst, f0, f1, f2, f3);
                    upk2(fmul2(q1.x, ampd), f0, f1);
                    upk2(fmul2(q1.y, ampd), f2, f3);
                    red4(dst + 4, f0, f1, f2, f3);
                    upk2(fmul2(q2.x, ampd), f0, f1);
                    upk2(fmul2(q2.y, ampd), f2, f3);
                    red4(dst + 8, f0, f1, f2, f3);
                }
            }
        } else {
            // edge fallback: scalar atomics with per-pixel bounds
#pragma unroll
            for (int ky = 0; ky < KS; ky++) {
                const int yy = cy + ky - HALF;
                if ((unsigned)yy < (unsigned)BOX) {
                    float* row = img_b + (size_t)yy * BOX;
#pragma unroll
                    for (int kx = 0; kx < KS; kx++) {
                        const int xx = cx + kx - HALF;
                        if ((unsigned)xx < (unsigned)BOX)
                            atomicAdd(row + xx, amps * sK2[ky * KS + kx]);
                    }
                }
            }
        }
    }
}

extern "C" void kernel_launch(void* const* d_in, const int* in_sizes, int n_in,
                              void* d_out, int out_size)
{
    const float* z          = (const float*)d_in[0];
    const float* r          = (const float*)d_in[1];
    const float* pos        = (const float*)d_in[2];
    const float* amp        = (const float*)d_in[3];
    const float* linamp1_W  = (const float*)d_in[4];
    const float* ampblock_W = (const float*)d_in[5];
    const float* ampblock_b = (const float*)d_in[6];
    const float* linamp2_W  = (const float*)d_in[7];
    const float* linamp2_b  = (const float*)d_in[8];
    const float* lin0_W     = (const float*)d_in[9];
    const float* deform_W   = (const float*)d_in[10];
    const float* deform_b   = (const float*)d_in[11];
    const float* lin1a_W    = (const float*)d_in[12];
    const float* lin1b_W    = (const float*)d_in[13];
    const float* k2         = (const float*)d_in[14];
    const int*   dflag      = (const int*)d_in[15];

    const int B = in_sizes[0] / LATENT;       // 16
    const int P = in_sizes[2] / 3;            // 20000

    float* out = (float*)d_out;
    const long long img_elems = (long long)B * BOX * BOX;
    const long long aux_elems = (long long)B * P * 7;
    cudaMemsetAsync(out, 0, (size_t)img_elems * sizeof(float));

    float *out_pd = nullptr, *out_res = nullptr, *out_ac = nullptr;
    if ((long long)out_size >= img_elems + aux_elems) {
        out_pd  = out + img_elems;
        out_res = out_pd + (long long)B * P * 3;
        out_ac  = out_res + (long long)B * P * 3;
    }

    dim3 grid((P + 255) / 256, B);
    decoder_kernel<<<grid, 128>>>(z, r, pos, amp, linamp1_W, ampblock_W,
                                  ampblock_b, linamp2_W, linamp2_b, lin0_W,
                                  deform_W, deform_b, lin1a_W, lin1b_W, k2,
                                  dflag, out, out_pd, out_res, out_ac, P);
}